// round 16
// baseline (speedup 1.0000x reference)
#include <cuda_runtime.h>
#include <cuda_fp16.h>
#include <math.h>
#include <stdint.h>

// ---------------------------------------------------------------------------
// Problem constants (B=4, N=2048, D=2048, H=16, DK=128, R=32)
// ---------------------------------------------------------------------------
#define B_   4
#define N_   2048
#define D_   2048
#define H_   16
#define DK_  128
#define R_   32
#define M_   (B_ * N_)      // 8192
#define HR_  (H_ * R_)      // 512

// ---------------------------------------------------------------------------
// Device scratch (all plain fp16)
// ---------------------------------------------------------------------------
__device__ __half g_xh [(size_t)M_ * D_];
__device__ __half g_WU [(size_t)(2 * HR_) * D_];   // rows 0..511 WUq*qscale, 512..1023 WUk
__device__ __half g_Wvh[(size_t)D_ * D_];
__device__ __half g_Wph[(size_t)D_ * D_];
__device__ __half g_Qh [(size_t)B_ * H_ * N_ * R_];
__device__ __half g_Kh [(size_t)B_ * H_ * N_ * R_];
__device__ __half g_Vh [(size_t)B_ * H_ * N_ * DK_];
__device__ __half g_Zh [(size_t)M_ * D_];

// ---------------------------------------------------------------------------
// PTX wrappers (sm_80-era, valid on plain sm_103 target)
// ---------------------------------------------------------------------------
__device__ __forceinline__ uint32_t smem_u32(const void* p) {
    uint32_t a;
    asm("{ .reg .u64 t; cvta.to.shared.u64 t, %1; cvt.u32.u64 %0, t; }"
        : "=r"(a) : "l"(p));
    return a;
}
__device__ __forceinline__ void ldsm_x4(uint32_t* r, uint32_t addr) {
    asm volatile("ldmatrix.sync.aligned.m8n8.x4.shared.b16 {%0,%1,%2,%3}, [%4];"
                 : "=r"(r[0]), "=r"(r[1]), "=r"(r[2]), "=r"(r[3]) : "r"(addr));
}
__device__ __forceinline__ void ldsm_x2(uint32_t* r, uint32_t addr) {
    asm volatile("ldmatrix.sync.aligned.m8n8.x2.shared.b16 {%0,%1}, [%2];"
                 : "=r"(r[0]), "=r"(r[1]) : "r"(addr));
}
__device__ __forceinline__ void ldsm_x4_t(uint32_t* r, uint32_t addr) {
    asm volatile("ldmatrix.sync.aligned.m8n8.x4.trans.shared.b16 {%0,%1,%2,%3}, [%4];"
                 : "=r"(r[0]), "=r"(r[1]), "=r"(r[2]), "=r"(r[3]) : "r"(addr));
}
__device__ __forceinline__ void mma_f16(float* d, const uint32_t* a, const uint32_t* b) {
    asm volatile(
        "mma.sync.aligned.m16n8k16.row.col.f32.f16.f16.f32 "
        "{%0,%1,%2,%3}, {%4,%5,%6,%7}, {%8,%9}, {%0,%1,%2,%3};"
        : "+f"(d[0]), "+f"(d[1]), "+f"(d[2]), "+f"(d[3])
        : "r"(a[0]), "r"(a[1]), "r"(a[2]), "r"(a[3]), "r"(b[0]), "r"(b[1]));
}
__device__ __forceinline__ void cp16(uint32_t dst, const void* src) {
    asm volatile("cp.async.cg.shared.global [%0], [%1], 16;"
                 :: "r"(dst), "l"(src) : "memory");
}
#define CP_COMMIT() asm volatile("cp.async.commit_group;" ::: "memory")
#define CP_WAITG(n) asm volatile("cp.async.wait_group %0;" :: "n"(n) : "memory")

__device__ __forceinline__ uint32_t packh2(float x, float y) {
    __half2 hh = __floats2half2_rn(x, y);
    return *reinterpret_cast<uint32_t*>(&hh);
}

// ---------------------------------------------------------------------------
// Prep kernels
// ---------------------------------------------------------------------------
// One launch converts x, Wv, Wproj (ranges in float4 units).
__global__ void cvt3_f16_kernel(const float4* __restrict__ s0, uint2* __restrict__ d0, int n0,
                                const float4* __restrict__ s1, uint2* __restrict__ d1, int n1,
                                const float4* __restrict__ s2, uint2* __restrict__ d2, int n2)
{
    int i = blockIdx.x * 256 + threadIdx.x;
    const float4* s; uint2* d;
    if (i < n0)                { s = s0; d = d0; }
    else if (i < n0 + n1)      { s = s1; d = d1; i -= n0; }
    else if (i < n0 + n1 + n2) { s = s2; d = d2; i -= n0 + n1; }
    else return;
    float4 v = s[i];
    d[i] = make_uint2(packh2(v.x, v.y), packh2(v.z, v.w));
}

// build_wu v3: one thread = one (d, h), computes ALL 32 r values.
// W column read once (was 4x). z selects Wq (scaled) vs Wk.
// WU row layout: z*512 + h*32 + r.
__global__ void build_wu_kernel(const float* __restrict__ Wq,
                                const float* __restrict__ Wk,
                                const float* __restrict__ U,
                                __half* __restrict__ WU,
                                float qscale)
{
    __shared__ float Us[128][32];
    const int tid = threadIdx.x;
    const int d   = blockIdx.x * 256 + tid;
    const int h   = blockIdx.y;
    const int z   = blockIdx.z;
    const float* W = (z == 0) ? Wq : Wk;
    const float sc = (z == 0) ? qscale : 1.0f;

    for (int i = tid; i < 128 * 32; i += 256)
        Us[i >> 5][i & 31] = U[i];
    __syncthreads();

    const float* wcol = W + (size_t)h * DK_ * D_ + d;
    float acc[32];
#pragma unroll
    for (int j = 0; j < 32; j++) acc[j] = 0.f;
#pragma unroll 2
    for (int dk = 0; dk < DK_; dk++) {
        float w = wcol[(size_t)dk * D_];
#pragma unroll
        for (int j = 0; j < 32; j++) acc[j] = fmaf(w, Us[dk][j], acc[j]);
    }
    size_t base = (size_t)(z * HR_ + h * 32) * D_ + d;
#pragma unroll
    for (int j = 0; j < 32; j++)
        WU[base + (size_t)j * D_] = __float2half(acc[j] * sc);
}

// ---------------------------------------------------------------------------
// HMMA fp16 GEMM (single-pass): C = A * B^T, both plain fp16.
// CTA 128x128, BK=32, 8 warps (2x4), warp tile 64x32, 2-stage cp.async.
// MODE 0: fp32 C[m*NN+n]
// MODE 2: fp16 plain head-split (scaled) -> Ch
// MODE 3: fused Q|K head-split: n<512 -> Ch (Q), n>=512 -> Ch2 (K); SPLIT=32
// ---------------------------------------------------------------------------
#define SGS 20480u
#define GEMM_SMEM (2 * 20480)

template <int MODE, int SPLIT>
__global__ void __launch_bounds__(256, 2)
gemm_f16(const __half* __restrict__ A_,
         const __half* __restrict__ B_x,
         float* __restrict__ Cf,
         __half* __restrict__ Ch,
         __half* __restrict__ Ch2,
         int NN, int K, float scale)
{
    extern __shared__ char sm[];
    const uint32_t sb = smem_u32(sm);

    const int tid  = threadIdx.x;
    const int lane = tid & 31;
    const int wid  = tid >> 5;
    const int wm   = wid & 1;
    const int wn   = wid >> 1;
    const int m0   = blockIdx.y * 128;
    const int n0   = blockIdx.x * 128;

    const __half* bases[2] = { A_ + (size_t)m0 * K, B_x + (size_t)n0 * K };

    auto issue = [&](int st, int it) {
        const uint32_t stb = sb + (uint32_t)st * SGS;
#pragma unroll
        for (int v = 0; v < 4; v++) {
            const int p = v >> 1;
            int rq = (v & 1) * 256 + tid;
            int r  = rq >> 2, q = rq & 3;
            const __half* src = bases[p] + (size_t)r * K + it * 32 + q * 8;
            cp16(stb + (uint32_t)(p * 10240 + r * 80 + q * 16), src);
        }
    };

    const int niter = K / 32;
    issue(0, 0); CP_COMMIT();
    issue(1, 1); CP_COMMIT();

    float acc[4][4][4];
#pragma unroll
    for (int mi = 0; mi < 4; mi++)
#pragma unroll
        for (int ni = 0; ni < 4; ni++)
#pragma unroll
            for (int f = 0; f < 4; f++) acc[mi][ni][f] = 0.f;

    const uint32_t a_off =
        (uint32_t)((wm * 64 + (lane & 15)) * 80 + (lane >> 4) * 16);
    const uint32_t b_off = 10240u +
        (uint32_t)((wn * 32 + (lane & 7)) * 80 + ((lane >> 3) & 1) * 16);

    for (int it = 0; it < niter; ++it) {
        CP_WAITG(1);
        __syncthreads();
        const uint32_t stb = sb + (uint32_t)(it & 1) * SGS;
        const uint32_t a_addr = stb + a_off;
        const uint32_t b_addr = stb + b_off;

#pragma unroll
        for (int ks = 0; ks < 2; ks++) {
            uint32_t ah[4][4];
#pragma unroll
            for (int mi = 0; mi < 4; mi++)
                ldsm_x4(ah[mi], a_addr + (uint32_t)(mi * 1280 + ks * 32));
#pragma unroll
            for (int ni = 0; ni < 4; ni++) {
                uint32_t bh[2];
                ldsm_x2(bh, b_addr + (uint32_t)(ni * 640 + ks * 32));
#pragma unroll
                for (int mi = 0; mi < 4; mi++)
                    mma_f16(acc[mi][ni], ah[mi], bh);
            }
        }
        __syncthreads();
        if (it + 2 < niter) { issue(it & 1, it + 2); CP_COMMIT(); }
    }

    const int g  = lane >> 2;
    const int c2 = (lane & 3) * 2;
#pragma unroll
    for (int mi = 0; mi < 4; mi++) {
#pragma unroll
        for (int ni = 0; ni < 4; ni++) {
            int m = m0 + wm * 64 + mi * 16 + g;
            int n = n0 + wn * 32 + ni * 8 + c2;
#pragma unroll
            for (int half_ = 0; half_ < 2; half_++) {
                int mm = m + half_ * 8;
                float v0 = acc[mi][ni][half_ * 2];
                float v1 = acc[mi][ni][half_ * 2 + 1];
                if (MODE == 0) {
                    *(float2*)(Cf + (size_t)mm * NN + n) = make_float2(v0, v1);
                } else if (MODE == 2) {
                    int b_ = mm >> 11;
                    int t  = mm & (N_ - 1);
                    int h  = n / SPLIT;
                    int j  = n % SPLIT;
                    size_t off = (((size_t)(b_ * H_ + h)) * N_ + t) * SPLIT + j;
                    *(uint32_t*)(Ch + off) = packh2(v0 * scale, v1 * scale);
                } else {  // MODE 3: fused Q|K (SPLIT=32; scale pre-folded)
                    __half* dst = (n < HR_) ? Ch : Ch2;
                    int nl = n & (HR_ - 1);
                    int b_ = mm >> 11;
                    int t  = mm & (N_ - 1);
                    int h  = nl >> 5;
                    int j  = nl & 31;
                    size_t off = (((size_t)(b_ * H_ + h)) * N_ + t) * 32 + j;
                    *(uint32_t*)(dst + off) = packh2(v0, v1);
                }
            }
        }
    }
}

// ---------------------------------------------------------------------------
// HMMA flash attention (unchanged from R15): 128 threads, 64 q-rows/CTA,
// 2 CTAs/SM; all plain fp16, single-pass S and PV.
// smem: Q 5120 | K stages 2x10240 | V stages 2x34816 = 95232 B
// ---------------------------------------------------------------------------
#define FQ 0
#define FK_BASE 5120
#define FK_STAGE 10240
#define FV_BASE 25600
#define FV_STAGE 34816
#define FLM_SMEM 95232
#define VSTR 272

__global__ void __launch_bounds__(128, 2)
flash_f16_kernel(const __half* __restrict__ Qh,
                 const __half* __restrict__ Kh,
                 const __half* __restrict__ Vh,
                 __half* __restrict__ Zh)
{
    extern __shared__ char sm[];
    const uint32_t sb = smem_u32(sm);

    const int tid  = threadIdx.x;
    const int lane = tid & 31;
    const int wq   = tid >> 5;
    const int bh   = blockIdx.y;
    const int h    = bh & (H_ - 1);
    const int b_   = bh >> 4;
    const int q0   = blockIdx.x * 64;
    const int g    = lane >> 2;
    const int t4   = lane & 3;

    const float slope = exp2f(-0.5f * (float)(h + 1));
    const float NEG_INF = -__int_as_float(0x7f800000);

    auto issue_kv = [&](int st, int kt2) {
        const int k0 = kt2 * 128;
        const __half* kh = Kh + ((size_t)bh * N_ + k0) * R_;
#pragma unroll
        for (int v = 0; v < 4; v++) {
            int idx = v * 128 + tid;
            int row = idx >> 2, q = idx & 3;
            cp16(sb + FK_BASE + st * FK_STAGE + (uint32_t)(row * 80 + q * 16),
                 kh + (size_t)row * R_ + q * 8);
        }
        const __half* vh = Vh + ((size_t)bh * N_ + k0) * DK_;
#pragma unroll
        for (int v = 0; v < 16; v++) {
            int idx = v * 128 + tid;
            int row = idx >> 4, q = idx & 15;
            cp16(sb + FV_BASE + st * FV_STAGE + (uint32_t)(row * VSTR + q * 16),
                 vh + (size_t)row * DK_ + q * 8);
        }
    };

    {
        const __half* qg = Qh + ((size_t)bh * N_ + q0) * R_;
#pragma unroll
        for (int v = 0; v < 2; v++) {
            int idx = v * 128 + tid;
            int row = idx >> 2, q = idx & 3;
            cp16(sb + FQ + (uint32_t)(row * 80 + q * 16),
                 qg + (size_t)row * R_ + q * 8);
        }
    }
    CP_COMMIT();
    issue_kv(0, 0); CP_COMMIT();
    issue_kv(1, 1); CP_COMMIT();

    CP_WAITG(2);
    __syncthreads();

    uint32_t qf[2][4];
    {
        uint32_t qaddr = sb + FQ +
            (uint32_t)((wq * 16 + (lane & 15)) * 80 + (lane >> 4) * 16);
#pragma unroll
        for (int ks = 0; ks < 2; ks++)
            ldsm_x4(qf[ks], qaddr + ks * 32);
    }

    float o[16][4];
#pragma unroll
    for (int d = 0; d < 16; d++)
#pragma unroll
        for (int f = 0; f < 4; f++) o[d][f] = 0.f;
    float m_i[2] = {NEG_INF, NEG_INF};
    float l_i[2] = {0.f, 0.f};

    for (int kt = 0; kt < N_ / 128; kt++) {
        const int k0 = kt * 128;
        CP_WAITG(1);
        __syncthreads();
        const int st = kt & 1;

        float s[16][4];
#pragma unroll
        for (int nb = 0; nb < 16; nb++)
#pragma unroll
            for (int f = 0; f < 4; f++) s[nb][f] = 0.f;

        {
            uint32_t baddr = sb + FK_BASE + st * FK_STAGE +
                (uint32_t)((lane & 7) * 80 + ((lane >> 3) & 1) * 16);
#pragma unroll
            for (int ks = 0; ks < 2; ks++) {
#pragma unroll
                for (int nb = 0; nb < 16; nb++) {
                    uint32_t bhh[2];
                    ldsm_x2(bhh, baddr + (uint32_t)(nb * 640 + ks * 32));
                    mma_f16(s[nb], qf[ks], bhh);
                }
            }
        }

#pragma unroll
        for (int nb = 0; nb < 16; nb++) {
#pragma unroll
            for (int f = 0; f < 4; f++) {
                int r = f >> 1, c = f & 1;
                int jg = k0 + nb * 8 + t4 * 2 + c;
                int ig = q0 + wq * 16 + g + r * 8;
                s[nb][f] -= slope * fmaxf((float)(jg - ig), 0.f);
            }
        }

        float alpha[2], mnew[2];
#pragma unroll
        for (int r = 0; r < 2; r++) {
            float tm = NEG_INF;
#pragma unroll
            for (int nb = 0; nb < 16; nb++) {
                tm = fmaxf(tm, s[nb][r * 2]);
                tm = fmaxf(tm, s[nb][r * 2 + 1]);
            }
            tm = fmaxf(tm, __shfl_xor_sync(0xffffffffu, tm, 1));
            tm = fmaxf(tm, __shfl_xor_sync(0xffffffffu, tm, 2));
            mnew[r]  = fmaxf(m_i[r], tm);
            alpha[r] = __expf(m_i[r] - mnew[r]);
            m_i[r]   = mnew[r];
        }

        float rsum[2] = {0.f, 0.f};
#pragma unroll
        for (int nb = 0; nb < 16; nb++) {
#pragma unroll
            for (int f = 0; f < 4; f++) {
                int r = f >> 1;
                float p = __expf(s[nb][f] - mnew[r]);
                s[nb][f] = p;
                rsum[r] += p;
            }
        }
#pragma unroll
        for (int r = 0; r < 2; r++) {
            rsum[r] += __shfl_xor_sync(0xffffffffu, rsum[r], 1);
            rsum[r] += __shfl_xor_sync(0xffffffffu, rsum[r], 2);
            l_i[r] = l_i[r] * alpha[r] + rsum[r];
        }
#pragma unroll
        for (int d = 0; d < 16; d++)
#pragma unroll
            for (int f = 0; f < 4; f++) o[d][f] *= alpha[f >> 1];

        {
            uint32_t vaddr = sb + FV_BASE + st * FV_STAGE +
                (uint32_t)((lane & 15) * VSTR + (lane >> 4) * 16);
#pragma unroll
            for (int ks = 0; ks < 8; ks++) {
                uint32_t aP[4];
                aP[0] = packh2(s[2 * ks][0],     s[2 * ks][1]);
                aP[1] = packh2(s[2 * ks][2],     s[2 * ks][3]);
                aP[2] = packh2(s[2 * ks + 1][0], s[2 * ks + 1][1]);
                aP[3] = packh2(s[2 * ks + 1][2], s[2 * ks + 1][3]);
#pragma unroll
                for (int db = 0; db < 8; db++) {
                    uint32_t vh4[4];
                    ldsm_x4_t(vh4, vaddr + (uint32_t)(ks * 16 * VSTR + db * 32));
                    mma_f16(o[db * 2],     aP, vh4);
                    mma_f16(o[db * 2 + 1], aP, vh4 + 2);
                }
            }
        }
        __syncthreads();
        if (kt + 2 < N_ / 128) { issue_kv(st, kt + 2); CP_COMMIT(); }
    }

    float inv[2] = {1.f / l_i[0], 1.f / l_i[1]};
#pragma unroll
    for (int db = 0; db < 16; db++) {
#pragma unroll
        for (int r = 0; r < 2; r++) {
            int row = q0 + wq * 16 + g + r * 8;
            size_t zoff = ((size_t)b_ * N_ + row) * D_ + h * DK_ + db * 8 + t4 * 2;
            *(uint32_t*)(Zh + zoff) =
                packh2(o[db][r * 2] * inv[r], o[db][r * 2 + 1] * inv[r]);
        }
    }
}

// ---------------------------------------------------------------------------
// Host launcher (graph-capturable: kernel launches only)
// ---------------------------------------------------------------------------
extern "C" void kernel_launch(void* const* d_in, const int* in_sizes, int n_in,
                              void* d_out, int out_size)
{
    (void)in_sizes; (void)n_in; (void)out_size;
    const float* x     = (const float*)d_in[0];
    const float* Wq    = (const float*)d_in[1];
    const float* Wk    = (const float*)d_in[2];
    const float* Wv    = (const float*)d_in[3];
    const float* U     = (const float*)d_in[4];
    const float* Wproj = (const float*)d_in[5];
    float* out = (float*)d_out;

    __half *xh, *WU, *Wvh, *Wph, *Qh, *Kh, *Vh, *Zh;
    cudaGetSymbolAddress((void**)&xh,  g_xh);
    cudaGetSymbolAddress((void**)&WU,  g_WU);
    cudaGetSymbolAddress((void**)&Wvh, g_Wvh);
    cudaGetSymbolAddress((void**)&Wph, g_Wph);
    cudaGetSymbolAddress((void**)&Qh,  g_Qh);
    cudaGetSymbolAddress((void**)&Kh,  g_Kh);
    cudaGetSymbolAddress((void**)&Vh,  g_Vh);
    cudaGetSymbolAddress((void**)&Zh,  g_Zh);

    cudaFuncSetAttribute(gemm_f16<3, R_>,
                         cudaFuncAttributeMaxDynamicSharedMemorySize, GEMM_SMEM);
    cudaFuncSetAttribute(gemm_f16<2, DK_>,
                         cudaFuncAttributeMaxDynamicSharedMemorySize, GEMM_SMEM);
    cudaFuncSetAttribute(gemm_f16<0, 1>,
                         cudaFuncAttributeMaxDynamicSharedMemorySize, GEMM_SMEM);
    cudaFuncSetAttribute(flash_f16_kernel,
                         cudaFuncAttributeMaxDynamicSharedMemorySize, FLM_SMEM);

    const float qscale = rsqrtf((float)DK_);

    // 0) fused conversions + fused U-folding (WUq pre-scaled, concatenated)
    {
        const int n0 = M_ * D_ / 4, n1 = D_ * D_ / 4, n2 = D_ * D_ / 4;
        const int total = n0 + n1 + n2;
        cvt3_f16_kernel<<<(total + 255) / 256, 256>>>(
            (const float4*)x,     (uint2*)xh,  n0,
            (const float4*)Wv,    (uint2*)Wvh, n1,
            (const float4*)Wproj, (uint2*)Wph, n2);
    }
    build_wu_kernel<<<dim3(D_ / 256, H_, 2), 256>>>(Wq, Wk, U, WU, qscale);

    // 1+2) fused Q|K = x @ WU^T -> plain fp16 [b,h,n,r] each (Q pre-scaled)
    gemm_f16<3, R_><<<dim3(2 * HR_ / 128, M_ / 128), 256, GEMM_SMEM>>>(
        xh, WU, nullptr, Qh, Kh, 2 * HR_, D_, 1.0f);
    // 3) V = x @ Wv^T -> plain fp16 [b,h,n,dk]
    gemm_f16<2, DK_><<<dim3(D_ / 128, M_ / 128), 256, GEMM_SMEM>>>(
        xh, Wvh, nullptr, Vh, nullptr, D_, D_, 1.0f);

    // 4) flash attention with ALiBi -> Z plain fp16 [b,n,d]
    flash_f16_kernel<<<dim3(N_ / 64, B_ * H_), 128, FLM_SMEM>>>(
        Qh, Kh, Vh, Zh);

    // 5) out = Z @ Wproj^T -> fp32
    gemm_f16<0, 1><<<dim3(D_ / 128, M_ / 128), 256, GEMM_SMEM>>>(
        Zh, Wph, out, nullptr, nullptr, D_, D_, 1.0f);
}

// round 17
// speedup vs baseline: 1.0012x; 1.0012x over previous
#include <cuda_runtime.h>
#include <cuda_fp16.h>
#include <math.h>
#include <stdint.h>

// ---------------------------------------------------------------------------
// Problem constants (B=4, N=2048, D=2048, H=16, DK=128, R=32)
// ---------------------------------------------------------------------------
#define B_   4
#define N_   2048
#define D_   2048
#define H_   16
#define DK_  128
#define R_   32
#define M_   (B_ * N_)      // 8192
#define HR_  (H_ * R_)      // 512

// ---------------------------------------------------------------------------
// Device scratch (all plain fp16)
// ---------------------------------------------------------------------------
__device__ __half g_xh  [(size_t)M_ * D_];
__device__ __half g_WUqh[(size_t)HR_ * D_];
__device__ __half g_WUkh[(size_t)HR_ * D_];
__device__ __half g_Wvh [(size_t)D_ * D_];
__device__ __half g_Wph [(size_t)D_ * D_];
__device__ __half g_Qh  [(size_t)B_ * H_ * N_ * R_];
__device__ __half g_Kh  [(size_t)B_ * H_ * N_ * R_];
__device__ __half g_Vh  [(size_t)B_ * H_ * N_ * DK_];
__device__ __half g_Zh  [(size_t)M_ * D_];

// ---------------------------------------------------------------------------
// PTX wrappers (sm_80-era, valid on plain sm_103 target)
// ---------------------------------------------------------------------------
__device__ __forceinline__ uint32_t smem_u32(const void* p) {
    uint32_t a;
    asm("{ .reg .u64 t; cvta.to.shared.u64 t, %1; cvt.u32.u64 %0, t; }"
        : "=r"(a) : "l"(p));
    return a;
}
__device__ __forceinline__ void ldsm_x4(uint32_t* r, uint32_t addr) {
    asm volatile("ldmatrix.sync.aligned.m8n8.x4.shared.b16 {%0,%1,%2,%3}, [%4];"
                 : "=r"(r[0]), "=r"(r[1]), "=r"(r[2]), "=r"(r[3]) : "r"(addr));
}
__device__ __forceinline__ void ldsm_x2(uint32_t* r, uint32_t addr) {
    asm volatile("ldmatrix.sync.aligned.m8n8.x2.shared.b16 {%0,%1}, [%2];"
                 : "=r"(r[0]), "=r"(r[1]) : "r"(addr));
}
__device__ __forceinline__ void ldsm_x4_t(uint32_t* r, uint32_t addr) {
    asm volatile("ldmatrix.sync.aligned.m8n8.x4.trans.shared.b16 {%0,%1,%2,%3}, [%4];"
                 : "=r"(r[0]), "=r"(r[1]), "=r"(r[2]), "=r"(r[3]) : "r"(addr));
}
__device__ __forceinline__ void mma_f16(float* d, const uint32_t* a, const uint32_t* b) {
    asm volatile(
        "mma.sync.aligned.m16n8k16.row.col.f32.f16.f16.f32 "
        "{%0,%1,%2,%3}, {%4,%5,%6,%7}, {%8,%9}, {%0,%1,%2,%3};"
        : "+f"(d[0]), "+f"(d[1]), "+f"(d[2]), "+f"(d[3])
        : "r"(a[0]), "r"(a[1]), "r"(a[2]), "r"(a[3]), "r"(b[0]), "r"(b[1]));
}
__device__ __forceinline__ void cp16(uint32_t dst, const void* src) {
    asm volatile("cp.async.cg.shared.global [%0], [%1], 16;"
                 :: "r"(dst), "l"(src) : "memory");
}
#define CP_COMMIT() asm volatile("cp.async.commit_group;" ::: "memory")
#define CP_WAITG(n) asm volatile("cp.async.wait_group %0;" :: "n"(n) : "memory")

__device__ __forceinline__ uint32_t packh2(float x, float y) {
    __half2 hh = __floats2half2_rn(x, y);
    return *reinterpret_cast<uint32_t*>(&hh);
}

// ---------------------------------------------------------------------------
// Prep kernels (R15-proven)
// ---------------------------------------------------------------------------
__global__ void cvt3_f16_kernel(const float4* __restrict__ s0, uint2* __restrict__ d0, int n0,
                                const float4* __restrict__ s1, uint2* __restrict__ d1, int n1,
                                const float4* __restrict__ s2, uint2* __restrict__ d2, int n2)
{
    int i = blockIdx.x * 256 + threadIdx.x;
    const float4* s; uint2* d;
    if (i < n0)                { s = s0; d = d0; }
    else if (i < n0 + n1)      { s = s1; d = d1; i -= n0; }
    else if (i < n0 + n1 + n2) { s = s2; d = d2; i -= n0 + n1; }
    else return;
    float4 v = s[i];
    d[i] = make_uint2(packh2(v.x, v.y), packh2(v.z, v.w));
}

// Fused WUq/WUk: z in 0..7; z<4 -> (Wq, WUq, rg=z), else (Wk, WUk, rg=z-4)
__global__ void build_wu_kernel(const float* __restrict__ Wq,
                                const float* __restrict__ Wk,
                                const float* __restrict__ U,
                                __half* __restrict__ WUq_,
                                __half* __restrict__ WUk_)
{
    __shared__ float Us[128][8];
    const int tid = threadIdx.x;
    const int d   = blockIdx.x * 256 + tid;
    const int h   = blockIdx.y;
    const int z   = blockIdx.z;
    const int rg  = z & 3;
    const float* W = (z < 4) ? Wq : Wk;
    __half* WUh    = (z < 4) ? WUq_ : WUk_;

    for (int i = tid; i < 128 * 8; i += 256) {
        int dk = i >> 3, j = i & 7;
        Us[dk][j] = U[dk * R_ + rg * 8 + j];
    }
    __syncthreads();

    const float* wcol = W + (size_t)h * DK_ * D_ + d;
    float acc[8];
#pragma unroll
    for (int j = 0; j < 8; j++) acc[j] = 0.f;
#pragma unroll 4
    for (int dk = 0; dk < DK_; dk++) {
        float w = wcol[(size_t)dk * D_];
#pragma unroll
        for (int j = 0; j < 8; j++) acc[j] = fmaf(w, Us[dk][j], acc[j]);
    }
#pragma unroll
    for (int j = 0; j < 8; j++) {
        size_t off = (size_t)(h * 32 + rg * 8 + j) * D_ + d;
        WUh[off] = __float2half(acc[j]);
    }
}

// ---------------------------------------------------------------------------
// HMMA fp16 GEMM v6: CTA 128x128, 128 threads (4 warps as 2Mx2N), warp tile
// 64x64, BK=32, 2-stage cp.async, 2 CTAs/SM.
// Crossbar math: A,B each read by 2 warps -> 64KB ldsm + 32KB cp-writes per
// SM-iter vs 512cyc MMA -> tensor ~67% (was 46%).
// MODE 0: fp32 C[m*NN+n];  MODE 2: fp16 plain head-split (scaled)
// ---------------------------------------------------------------------------
#define SGS 20480u
#define GEMM_SMEM (2 * 20480)

template <int MODE, int SPLIT>
__global__ void __launch_bounds__(128, 2)
gemm_f16(const __half* __restrict__ A_,
         const __half* __restrict__ B_x,
         float* __restrict__ Cf,
         __half* __restrict__ Ch,
         int NN, int K, float scale)
{
    extern __shared__ char sm[];
    const uint32_t sb = smem_u32(sm);

    const int tid  = threadIdx.x;
    const int lane = tid & 31;
    const int wid  = tid >> 5;
    const int wm   = wid & 1;      // 0..1 : 64 M-rows
    const int wn   = wid >> 1;     // 0..1 : 64 N-cols
    const int m0   = blockIdx.y * 128;
    const int n0   = blockIdx.x * 128;

    const __half* bases[2] = { A_ + (size_t)m0 * K, B_x + (size_t)n0 * K };

    // 1024 16B chunks per stage, 128 threads -> 8 per thread
    auto issue = [&](int st, int it) {
        const uint32_t stb = sb + (uint32_t)st * SGS;
#pragma unroll
        for (int v = 0; v < 8; v++) {
            const int p = v >> 2;              // part: 0=A, 1=B
            int rq = (v & 3) * 128 + tid;      // 0..511
            int r  = rq >> 2, q = rq & 3;
            const __half* src = bases[p] + (size_t)r * K + it * 32 + q * 8;
            cp16(stb + (uint32_t)(p * 10240 + r * 80 + q * 16), src);
        }
    };

    const int niter = K / 32;
    issue(0, 0); CP_COMMIT();
    issue(1, 1); CP_COMMIT();

    float acc[4][8][4];
#pragma unroll
    for (int mi = 0; mi < 4; mi++)
#pragma unroll
        for (int ni = 0; ni < 8; ni++)
#pragma unroll
            for (int f = 0; f < 4; f++) acc[mi][ni][f] = 0.f;

    const uint32_t a_off =
        (uint32_t)((wm * 64 + (lane & 15)) * 80 + (lane >> 4) * 16);
    const uint32_t b_off = 10240u +
        (uint32_t)((wn * 64 + (lane & 15)) * 80 + (lane >> 4) * 16);

    for (int it = 0; it < niter; ++it) {
        CP_WAITG(1);
        __syncthreads();
        const uint32_t stb = sb + (uint32_t)(it & 1) * SGS;
        const uint32_t a_addr = stb + a_off;
        const uint32_t b_addr = stb + b_off;

#pragma unroll
        for (int ks = 0; ks < 2; ks++) {
            uint32_t ah[4][4];
#pragma unroll
            for (int mi = 0; mi < 4; mi++)
                ldsm_x4(ah[mi], a_addr + (uint32_t)(mi * 1280 + ks * 32));
#pragma unroll
            for (int nj = 0; nj < 4; nj++) {
                // x4 over 16 B-rows: r={n0-7 k0-7, n8-15 k0-7, n0-7 k8-15, n8-15 k8-15}
                uint32_t bq[4];
                ldsm_x4(bq, b_addr + (uint32_t)(nj * 1280 + ks * 32));
                uint32_t b0[2] = { bq[0], bq[2] };   // ni = 2*nj
                uint32_t b1[2] = { bq[1], bq[3] };   // ni = 2*nj+1
#pragma unroll
                for (int mi = 0; mi < 4; mi++) {
                    mma_f16(acc[mi][2 * nj],     ah[mi], b0);
                    mma_f16(acc[mi][2 * nj + 1], ah[mi], b1);
                }
            }
        }
        __syncthreads();
        if (it + 2 < niter) { issue(it & 1, it + 2); CP_COMMIT(); }
    }

    // epilogue
    const int g  = lane >> 2;
    const int c2 = (lane & 3) * 2;
#pragma unroll
    for (int mi = 0; mi < 4; mi++) {
#pragma unroll
        for (int ni = 0; ni < 8; ni++) {
            int m = m0 + wm * 64 + mi * 16 + g;
            int n = n0 + wn * 64 + ni * 8 + c2;
#pragma unroll
            for (int half_ = 0; half_ < 2; half_++) {
                int mm = m + half_ * 8;
                float v0 = acc[mi][ni][half_ * 2];
                float v1 = acc[mi][ni][half_ * 2 + 1];
                if (MODE == 0) {
                    *(float2*)(Cf + (size_t)mm * NN + n) = make_float2(v0, v1);
                } else {
                    int b_ = mm >> 11;
                    int t  = mm & (N_ - 1);
                    int h  = n / SPLIT;
                    int j  = n % SPLIT;
                    size_t off = (((size_t)(b_ * H_ + h)) * N_ + t) * SPLIT + j;
                    *(uint32_t*)(Ch + off) = packh2(v0 * scale, v1 * scale);
                }
            }
        }
    }
}

// ---------------------------------------------------------------------------
// HMMA flash attention (unchanged from R15): 128 threads, 64 q-rows/CTA,
// 2 CTAs/SM; all plain fp16, single-pass S and PV.
// smem: Q 5120 | K stages 2x10240 | V stages 2x34816 = 95232 B
// ---------------------------------------------------------------------------
#define FQ 0
#define FK_BASE 5120
#define FK_STAGE 10240
#define FV_BASE 25600
#define FV_STAGE 34816
#define FLM_SMEM 95232
#define VSTR 272

__global__ void __launch_bounds__(128, 2)
flash_f16_kernel(const __half* __restrict__ Qh,
                 const __half* __restrict__ Kh,
                 const __half* __restrict__ Vh,
                 __half* __restrict__ Zh)
{
    extern __shared__ char sm[];
    const uint32_t sb = smem_u32(sm);

    const int tid  = threadIdx.x;
    const int lane = tid & 31;
    const int wq   = tid >> 5;
    const int bh   = blockIdx.y;
    const int h    = bh & (H_ - 1);
    const int b_   = bh >> 4;
    const int q0   = blockIdx.x * 64;
    const int g    = lane >> 2;
    const int t4   = lane & 3;

    const float slope = exp2f(-0.5f * (float)(h + 1));
    const float NEG_INF = -__int_as_float(0x7f800000);

    auto issue_kv = [&](int st, int kt2) {
        const int k0 = kt2 * 128;
        const __half* kh = Kh + ((size_t)bh * N_ + k0) * R_;
#pragma unroll
        for (int v = 0; v < 4; v++) {
            int idx = v * 128 + tid;
            int row = idx >> 2, q = idx & 3;
            cp16(sb + FK_BASE + st * FK_STAGE + (uint32_t)(row * 80 + q * 16),
                 kh + (size_t)row * R_ + q * 8);
        }
        const __half* vh = Vh + ((size_t)bh * N_ + k0) * DK_;
#pragma unroll
        for (int v = 0; v < 16; v++) {
            int idx = v * 128 + tid;
            int row = idx >> 4, q = idx & 15;
            cp16(sb + FV_BASE + st * FV_STAGE + (uint32_t)(row * VSTR + q * 16),
                 vh + (size_t)row * DK_ + q * 8);
        }
    };

    {
        const __half* qg = Qh + ((size_t)bh * N_ + q0) * R_;
#pragma unroll
        for (int v = 0; v < 2; v++) {
            int idx = v * 128 + tid;
            int row = idx >> 2, q = idx & 3;
            cp16(sb + FQ + (uint32_t)(row * 80 + q * 16),
                 qg + (size_t)row * R_ + q * 8);
        }
    }
    CP_COMMIT();
    issue_kv(0, 0); CP_COMMIT();
    issue_kv(1, 1); CP_COMMIT();

    CP_WAITG(2);
    __syncthreads();

    uint32_t qf[2][4];
    {
        uint32_t qaddr = sb + FQ +
            (uint32_t)((wq * 16 + (lane & 15)) * 80 + (lane >> 4) * 16);
#pragma unroll
        for (int ks = 0; ks < 2; ks++)
            ldsm_x4(qf[ks], qaddr + ks * 32);
    }

    float o[16][4];
#pragma unroll
    for (int d = 0; d < 16; d++)
#pragma unroll
        for (int f = 0; f < 4; f++) o[d][f] = 0.f;
    float m_i[2] = {NEG_INF, NEG_INF};
    float l_i[2] = {0.f, 0.f};

    for (int kt = 0; kt < N_ / 128; kt++) {
        const int k0 = kt * 128;
        CP_WAITG(1);
        __syncthreads();
        const int st = kt & 1;

        float s[16][4];
#pragma unroll
        for (int nb = 0; nb < 16; nb++)
#pragma unroll
            for (int f = 0; f < 4; f++) s[nb][f] = 0.f;

        {
            uint32_t baddr = sb + FK_BASE + st * FK_STAGE +
                (uint32_t)((lane & 7) * 80 + ((lane >> 3) & 1) * 16);
#pragma unroll
            for (int ks = 0; ks < 2; ks++) {
#pragma unroll
                for (int nb = 0; nb < 16; nb++) {
                    uint32_t bhh[2];
                    ldsm_x2(bhh, baddr + (uint32_t)(nb * 640 + ks * 32));
                    mma_f16(s[nb], qf[ks], bhh);
                }
            }
        }

#pragma unroll
        for (int nb = 0; nb < 16; nb++) {
#pragma unroll
            for (int f = 0; f < 4; f++) {
                int r = f >> 1, c = f & 1;
                int jg = k0 + nb * 8 + t4 * 2 + c;
                int ig = q0 + wq * 16 + g + r * 8;
                s[nb][f] -= slope * fmaxf((float)(jg - ig), 0.f);
            }
        }

        float alpha[2], mnew[2];
#pragma unroll
        for (int r = 0; r < 2; r++) {
            float tm = NEG_INF;
#pragma unroll
            for (int nb = 0; nb < 16; nb++) {
                tm = fmaxf(tm, s[nb][r * 2]);
                tm = fmaxf(tm, s[nb][r * 2 + 1]);
            }
            tm = fmaxf(tm, __shfl_xor_sync(0xffffffffu, tm, 1));
            tm = fmaxf(tm, __shfl_xor_sync(0xffffffffu, tm, 2));
            mnew[r]  = fmaxf(m_i[r], tm);
            alpha[r] = __expf(m_i[r] - mnew[r]);
            m_i[r]   = mnew[r];
        }

        float rsum[2] = {0.f, 0.f};
#pragma unroll
        for (int nb = 0; nb < 16; nb++) {
#pragma unroll
            for (int f = 0; f < 4; f++) {
                int r = f >> 1;
                float p = __expf(s[nb][f] - mnew[r]);
                s[nb][f] = p;
                rsum[r] += p;
            }
        }
#pragma unroll
        for (int r = 0; r < 2; r++) {
            rsum[r] += __shfl_xor_sync(0xffffffffu, rsum[r], 1);
            rsum[r] += __shfl_xor_sync(0xffffffffu, rsum[r], 2);
            l_i[r] = l_i[r] * alpha[r] + rsum[r];
        }
#pragma unroll
        for (int d = 0; d < 16; d++)
#pragma unroll
            for (int f = 0; f < 4; f++) o[d][f] *= alpha[f >> 1];

        {
            uint32_t vaddr = sb + FV_BASE + st * FV_STAGE +
                (uint32_t)((lane & 15) * VSTR + (lane >> 4) * 16);
#pragma unroll
            for (int ks = 0; ks < 8; ks++) {
                uint32_t aP[4];
                aP[0] = packh2(s[2 * ks][0],     s[2 * ks][1]);
                aP[1] = packh2(s[2 * ks][2],     s[2 * ks][3]);
                aP[2] = packh2(s[2 * ks + 1][0], s[2 * ks + 1][1]);
                aP[3] = packh2(s[2 * ks + 1][2], s[2 * ks + 1][3]);
#pragma unroll
                for (int db = 0; db < 8; db++) {
                    uint32_t vh4[4];
                    ldsm_x4_t(vh4, vaddr + (uint32_t)(ks * 16 * VSTR + db * 32));
                    mma_f16(o[db * 2],     aP, vh4);
                    mma_f16(o[db * 2 + 1], aP, vh4 + 2);
                }
            }
        }
        __syncthreads();
        if (kt + 2 < N_ / 128) { issue_kv(st, kt + 2); CP_COMMIT(); }
    }

    float inv[2] = {1.f / l_i[0], 1.f / l_i[1]};
#pragma unroll
    for (int db = 0; db < 16; db++) {
#pragma unroll
        for (int r = 0; r < 2; r++) {
            int row = q0 + wq * 16 + g + r * 8;
            size_t zoff = ((size_t)b_ * N_ + row) * D_ + h * DK_ + db * 8 + t4 * 2;
            *(uint32_t*)(Zh + zoff) =
                packh2(o[db][r * 2] * inv[r], o[db][r * 2 + 1] * inv[r]);
        }
    }
}

// ---------------------------------------------------------------------------
// Host launcher (graph-capturable: kernel launches only)
// ---------------------------------------------------------------------------
extern "C" void kernel_launch(void* const* d_in, const int* in_sizes, int n_in,
                              void* d_out, int out_size)
{
    (void)in_sizes; (void)n_in; (void)out_size;
    const float* x     = (const float*)d_in[0];
    const float* Wq    = (const float*)d_in[1];
    const float* Wk    = (const float*)d_in[2];
    const float* Wv    = (const float*)d_in[3];
    const float* U     = (const float*)d_in[4];
    const float* Wproj = (const float*)d_in[5];
    float* out = (float*)d_out;

    __half *xh, *WUqh, *WUkh, *Wvh, *Wph, *Qh, *Kh, *Vh, *Zh;
    cudaGetSymbolAddress((void**)&xh,   g_xh);
    cudaGetSymbolAddress((void**)&WUqh, g_WUqh);
    cudaGetSymbolAddress((void**)&WUkh, g_WUkh);
    cudaGetSymbolAddress((void**)&Wvh,  g_Wvh);
    cudaGetSymbolAddress((void**)&Wph,  g_Wph);
    cudaGetSymbolAddress((void**)&Qh,   g_Qh);
    cudaGetSymbolAddress((void**)&Kh,   g_Kh);
    cudaGetSymbolAddress((void**)&Vh,   g_Vh);
    cudaGetSymbolAddress((void**)&Zh,   g_Zh);

    cudaFuncSetAttribute(gemm_f16<2, R_>,
                         cudaFuncAttributeMaxDynamicSharedMemorySize, GEMM_SMEM);
    cudaFuncSetAttribute(gemm_f16<2, DK_>,
                         cudaFuncAttributeMaxDynamicSharedMemorySize, GEMM_SMEM);
    cudaFuncSetAttribute(gemm_f16<0, 1>,
                         cudaFuncAttributeMaxDynamicSharedMemorySize, GEMM_SMEM);
    cudaFuncSetAttribute(flash_f16_kernel,
                         cudaFuncAttributeMaxDynamicSharedMemorySize, FLM_SMEM);

    const float qscale = rsqrtf((float)DK_);

    // 0) fused conversions + fused U-folding (R15-proven)
    {
        const int n0 = M_ * D_ / 4, n1 = D_ * D_ / 4, n2 = D_ * D_ / 4;
        const int total = n0 + n1 + n2;
        cvt3_f16_kernel<<<(total + 255) / 256, 256>>>(
            (const float4*)x,     (uint2*)xh,  n0,
            (const float4*)Wv,    (uint2*)Wvh, n1,
            (const float4*)Wproj, (uint2*)Wph, n2);
    }
    build_wu_kernel<<<dim3(D_ / 256, H_, 8), 256>>>(Wq, Wk, U, WUqh, WUkh);

    // 1) Q = (x @ WUq^T) * 1/sqrt(dk) -> plain fp16 [b,h,n,r]
    gemm_f16<2, R_><<<dim3(HR_ / 128, M_ / 128), 128, GEMM_SMEM>>>(
        xh, WUqh, nullptr, Qh, HR_, D_, qscale);
    // 2) K = x @ WUk^T -> plain fp16
    gemm_f16<2, R_><<<dim3(HR_ / 128, M_ / 128), 128, GEMM_SMEM>>>(
        xh, WUkh, nullptr, Kh, HR_, D_, 1.0f);
    // 3) V = x @ Wv^T -> plain fp16 [b,h,n,dk]
    gemm_f16<2, DK_><<<dim3(D_ / 128, M_ / 128), 128, GEMM_SMEM>>>(
        xh, Wvh, nullptr, Vh, D_, D_, 1.0f);

    // 4) flash attention with ALiBi -> Z plain fp16 [b,n,d]
    flash_f16_kernel<<<dim3(N_ / 64, B_ * H_), 128, FLM_SMEM>>>(
        Qh, Kh, Vh, Zh);

    // 5) out = Z @ Wproj^T -> fp32
    gemm_f16<0, 1><<<dim3(D_ / 128, M_ / 128), 128, GEMM_SMEM>>>(
        Zh, Wph, out, nullptr, D_, D_, 1.0f);
}